// round 4
// baseline (speedup 1.0000x reference)
#include <cuda_runtime.h>
#include <cuda_bf16.h>
#include <cstdint>

#define N_MAX 100352
#define E_MAX 1000000
#define HID 64

// ---------------- device scratch ----------------
__device__ float g_H [100000 * HID];
__device__ float g_HW[100000 * HID];
__device__ float g_dinv[N_MAX];
__device__ int   g_hist[N_MAX];
__device__ int   g_offs[N_MAX];
__device__ int   g_cur [N_MAX];
__device__ int   g_part[256];
__device__ int   g_esrc[E_MAX];
__device__ int   g_is64;

// ---------------- f32x2 helpers ----------------
union U64F2 { unsigned long long u; float2 f; };

__device__ __forceinline__ unsigned long long pack2(float x, float y) {
    unsigned long long r;
    asm("mov.b64 %0, {%1,%2};" : "=l"(r) : "f"(x), "f"(y));
    return r;
}
__device__ __forceinline__ unsigned long long ffma2(unsigned long long a,
                                                    unsigned long long b,
                                                    unsigned long long c) {
    unsigned long long d;
    asm("fma.rn.f32x2 %0, %1, %2, %3;" : "=l"(d) : "l"(a), "l"(b), "l"(c));
    return d;
}

// ---------------- edge access ----------------
__device__ __forceinline__ int edge_at(const void* ei, int idx) {
    if (g_is64) return (int)((const long long*)ei)[idx];
    return ((const int*)ei)[idx];
}

// ---------------- zero hist + dtype detect (merged) ----------------
__global__ void k_zero_detect(const unsigned long long* __restrict__ ei, int n) {
    int i = blockIdx.x * blockDim.x + threadIdx.x;
    if (i < n) g_hist[i] = 0;
    if (blockIdx.x == 0) {
        int local = 0;
        for (int j = threadIdx.x; j < 1024; j += blockDim.x)
            if ((ei[j] >> 32) != 0ull) local = 1;
        int any = __syncthreads_or(local);
        if (threadIdx.x == 0) g_is64 = (any == 0);
    }
}

__global__ void k_hist(const void* __restrict__ ei, int E) {
    int e = blockIdx.x * blockDim.x + threadIdx.x;
    if (e < E) atomicAdd(&g_hist[edge_at(ei, E + e)], 1);
}

// ---------------- scan1 (+dinv merged) ----------------
__global__ void k_scan1(int n) {
    int idx = blockIdx.x * 512 + threadIdx.x;
    int v = (idx < n) ? g_hist[idx] : 0;
    if (idx < n) g_dinv[idx] = rsqrtf((float)v + 1.0f);   // +1 self loop
    int lane = threadIdx.x & 31, wid = threadIdx.x >> 5;
    int inc = v;
    #pragma unroll
    for (int o = 1; o < 32; o <<= 1) {
        int t = __shfl_up_sync(0xffffffffu, inc, o);
        if (lane >= o) inc += t;
    }
    __shared__ int wsum[16];
    if (lane == 31) wsum[wid] = inc;
    __syncthreads();
    if (wid == 0) {
        int s = (lane < 16) ? wsum[lane] : 0;
        #pragma unroll
        for (int o = 1; o < 16; o <<= 1) {
            int t = __shfl_up_sync(0xffffffffu, s, o);
            if (lane >= o) s += t;
        }
        if (lane < 16) wsum[lane] = s;
    }
    __syncthreads();
    int base = (wid > 0) ? wsum[wid - 1] : 0;
    if (idx < n) g_offs[idx] = base + inc - v;
    if (threadIdx.x == 0) g_part[blockIdx.x] = wsum[15];
}

__global__ void k_scan2(int nb) {
    int t = threadIdx.x;
    int v = (t < nb) ? g_part[t] : 0;
    int lane = t & 31, wid = t >> 5;
    int inc = v;
    #pragma unroll
    for (int o = 1; o < 32; o <<= 1) {
        int s = __shfl_up_sync(0xffffffffu, inc, o);
        if (lane >= o) inc += s;
    }
    __shared__ int wsum[8];
    if (lane == 31) wsum[wid] = inc;
    __syncthreads();
    if (wid == 0) {
        int s = (lane < 8) ? wsum[lane] : 0;
        #pragma unroll
        for (int o = 1; o < 8; o <<= 1) {
            int u = __shfl_up_sync(0xffffffffu, s, o);
            if (lane >= o) s += u;
        }
        if (lane < 8) wsum[lane] = s;
    }
    __syncthreads();
    int base = (wid > 0) ? wsum[wid - 1] : 0;
    if (t < nb) g_part[t] = base + inc - v;
}

__global__ void k_scan3(int n) {
    int idx = blockIdx.x * 512 + threadIdx.x;
    if (idx < n) {
        int o = g_offs[idx] + g_part[blockIdx.x];
        g_offs[idx] = o;
        g_cur[idx]  = o;
    }
}

__global__ void k_place(const void* __restrict__ ei, int E) {
    int e = blockIdx.x * blockDim.x + threadIdx.x;
    if (e < E) {
        int s = edge_at(ei, e);
        int d = edge_at(ei, E + e);
        int pos = atomicAdd(&g_cur[d], 1);
        g_esrc[pos] = s;
    }
}

// ---------------- GEMM (f32x2): C[n,64] = A[n,K] @ W[K,64] (+bias) -------
// 128x64 tile / block, 256 threads, thread = 4 rows x 8 cols (4 col-pairs).
__global__ __launch_bounds__(256) void k_gemm(
    const float* __restrict__ Aext, const float* __restrict__ W,
    const float* __restrict__ bias, int dst_hw, int n, int K)
{
    const float* A = Aext ? Aext : (const float*)g_H;
    float* C = dst_hw ? g_HW : g_H;

    __shared__ float As[128][64];   // 32 KB
    __shared__ float Ws[64][64];    // 16 KB
    int row0 = blockIdx.x * 128;
    int tid = threadIdx.x;
    int tr = tid >> 3;        // 0..31 -> rows tr*4 .. tr*4+3
    int tc = tid & 7;         // 0..7  -> cols tc*8 .. tc*8+7

    unsigned long long acc[4][4];   // [row][col-pair]
    #pragma unroll
    for (int r = 0; r < 4; r++)
        #pragma unroll
        for (int p = 0; p < 4; p++) acc[r][p] = 0ull;

    for (int k0 = 0; k0 < K; k0 += 64) {
        // A tile: 128 rows x 64 cols
        #pragma unroll
        for (int i = tid; i < 128 * 16; i += 256) {
            int r = i >> 4, c4 = (i & 15) << 2;
            int gr = row0 + r;
            float4 v = (gr < n) ? *(const float4*)(A + (size_t)gr * K + k0 + c4)
                                : make_float4(0.f, 0.f, 0.f, 0.f);
            *(float4*)&As[r][c4] = v;
        }
        // W tile: 64 x 64
        #pragma unroll
        for (int i = tid; i < 64 * 16; i += 256) {
            int r = i >> 4, c4 = (i & 15) << 2;
            *(float4*)&Ws[r][c4] = *(const float4*)(W + (size_t)(k0 + r) * 64 + c4);
        }
        __syncthreads();

        #pragma unroll
        for (int kk = 0; kk < 64; kk += 4) {
            float4 a[4];
            #pragma unroll
            for (int r = 0; r < 4; r++) a[r] = *(float4*)&As[tr * 4 + r][kk];
            #pragma unroll
            for (int j = 0; j < 4; j++) {
                float4 b0 = *(float4*)&Ws[kk + j][tc * 8];
                float4 b1 = *(float4*)&Ws[kk + j][tc * 8 + 4];
                unsigned long long bp0 = pack2(b0.x, b0.y);
                unsigned long long bp1 = pack2(b0.z, b0.w);
                unsigned long long bp2 = pack2(b1.x, b1.y);
                unsigned long long bp3 = pack2(b1.z, b1.w);
                #pragma unroll
                for (int r = 0; r < 4; r++) {
                    float av = (j == 0) ? a[r].x : (j == 1) ? a[r].y
                             : (j == 2) ? a[r].z : a[r].w;
                    unsigned long long ad = pack2(av, av);
                    acc[r][0] = ffma2(ad, bp0, acc[r][0]);
                    acc[r][1] = ffma2(ad, bp1, acc[r][1]);
                    acc[r][2] = ffma2(ad, bp2, acc[r][2]);
                    acc[r][3] = ffma2(ad, bp3, acc[r][3]);
                }
            }
        }
        __syncthreads();
    }

    float4 bb0 = make_float4(0.f, 0.f, 0.f, 0.f), bb1 = bb0;
    if (bias) {
        bb0 = *(const float4*)(bias + tc * 8);
        bb1 = *(const float4*)(bias + tc * 8 + 4);
    }
    #pragma unroll
    for (int r = 0; r < 4; r++) {
        int gr = row0 + tr * 4 + r;
        if (gr < n) {
            U64F2 p0, p1, p2, p3;
            p0.u = acc[r][0]; p1.u = acc[r][1]; p2.u = acc[r][2]; p3.u = acc[r][3];
            float4 o0 = make_float4(p0.f.x + bb0.x, p0.f.y + bb0.y,
                                    p1.f.x + bb0.z, p1.f.y + bb0.w);
            float4 o1 = make_float4(p2.f.x + bb1.x, p2.f.y + bb1.y,
                                    p3.f.x + bb1.z, p3.f.y + bb1.w);
            *(float4*)(C + (size_t)gr * 64 + tc * 8)     = o0;
            *(float4*)(C + (size_t)gr * 64 + tc * 8 + 4) = o1;
        }
    }
}

// ---------------- fused aggregate + bias + LN (+ReLU+residual) ----------
__global__ void k_agg(const float* __restrict__ bias, const float* __restrict__ gma,
                      const float* __restrict__ beta, float* __restrict__ out_ext,
                      int n, int relu_res)
{
    int node = (blockIdx.x * blockDim.x + threadIdx.x) >> 5;
    if (node >= n) return;
    int lane = threadIdx.x & 31;
    float* out = out_ext ? out_ext : (float*)g_H;

    float di = g_dinv[node];
    float2 acc = ((const float2*)(g_HW + (size_t)node * HID))[lane];
    float self = di * di;
    acc.x *= self; acc.y *= self;
    float2 accB = make_float2(0.f, 0.f);

    int e = g_offs[node];
    int e_end = e + g_hist[node];
    // 2-way unrolled: two independent gather chains in flight
    for (; e + 2 <= e_end; e += 2) {
        int sa = g_esrc[e];
        int sb = g_esrc[e + 1];
        float na = g_dinv[sa] * di;
        float nb = g_dinv[sb] * di;
        float2 va = ((const float2*)(g_HW + (size_t)sa * HID))[lane];
        float2 vb = ((const float2*)(g_HW + (size_t)sb * HID))[lane];
        acc.x  = fmaf(va.x, na, acc.x);  acc.y  = fmaf(va.y, na, acc.y);
        accB.x = fmaf(vb.x, nb, accB.x); accB.y = fmaf(vb.y, nb, accB.y);
    }
    if (e < e_end) {
        int sa = g_esrc[e];
        float na = g_dinv[sa] * di;
        float2 va = ((const float2*)(g_HW + (size_t)sa * HID))[lane];
        acc.x = fmaf(va.x, na, acc.x); acc.y = fmaf(va.y, na, acc.y);
    }
    acc.x += accB.x; acc.y += accB.y;

    float2 bb = ((const float2*)bias)[lane];
    acc.x += bb.x; acc.y += bb.y;

    float sum = acc.x + acc.y;
    #pragma unroll
    for (int o = 16; o; o >>= 1) sum += __shfl_xor_sync(0xffffffffu, sum, o);
    float mu = sum * (1.0f / 64.0f);
    float dx = acc.x - mu, dy = acc.y - mu;
    float vs = dx * dx + dy * dy;
    #pragma unroll
    for (int o = 16; o; o >>= 1) vs += __shfl_xor_sync(0xffffffffu, vs, o);
    float rstd = rsqrtf(vs * (1.0f / 64.0f) + 1e-5f);
    float2 gg = ((const float2*)gma)[lane];
    float2 be = ((const float2*)beta)[lane];
    float ox = dx * rstd * gg.x + be.x;
    float oy = dy * rstd * gg.y + be.y;

    if (relu_res) {
        float2 r = ((const float2*)(g_H + (size_t)node * HID))[lane];
        ox = fmaxf(ox, 0.0f) + r.x;
        oy = fmaxf(oy, 0.0f) + r.y;
    }
    ((float2*)(out + (size_t)node * HID))[lane] = make_float2(ox, oy);
}

// ---------------- launch ----------------
extern "C" void kernel_launch(void* const* d_in, const int* in_sizes, int n_in,
                              void* d_out, int out_size)
{
    const float* x      = (const float*)d_in[0];
    const void*  ei     = d_in[1];
    const float* proj_w = (const float*)d_in[2];
    const float* proj_b = (const float*)d_in[3];
    const float* w[3]  = { (const float*)d_in[4],  (const float*)d_in[8],  (const float*)d_in[12] };
    const float* b[3]  = { (const float*)d_in[5],  (const float*)d_in[9],  (const float*)d_in[13] };
    const float* gm[3] = { (const float*)d_in[6],  (const float*)d_in[10], (const float*)d_in[14] };
    const float* bt[3] = { (const float*)d_in[7],  (const float*)d_in[11], (const float*)d_in[15] };

    int n = in_sizes[0] / 128;    // 100000
    int E = in_sizes[1] / 2;      // 1000000
    float* out = (float*)d_out;

    int nb512 = (n + 511) / 512;

    // launch order chosen so slot 5 (-s 5 -c 1) = proj GEMM
    k_zero_detect<<<(n + 255) / 256, 256>>>((const unsigned long long*)ei, n);  // 0
    k_hist<<<(E + 255) / 256, 256>>>(ei, E);                                     // 1
    k_scan1<<<nb512, 512>>>(n);                                                  // 2
    k_scan2<<<1, 256>>>(nb512);                                                  // 3
    k_scan3<<<nb512, 512>>>(n);                                                  // 4
    k_gemm<<<(n + 127) / 128, 256>>>(x, proj_w, proj_b, /*dst_hw=*/0, n, 128);   // 5 (proj)
    k_place<<<(E + 255) / 256, 256>>>(ei, E);                                    // 6

    int agg_blocks = (n + 7) / 8;
    for (int l = 0; l < 3; l++) {
        k_gemm<<<(n + 127) / 128, 256>>>(nullptr, w[l], nullptr, /*dst_hw=*/1, n, 64);
        float* dst = (l < 2) ? nullptr : out;
        k_agg<<<agg_blocks, 256>>>(b[l], gm[l], bt[l], dst, n, (l < 2) ? 1 : 0);
    }
}

// round 5
// speedup vs baseline: 1.3485x; 1.3485x over previous
#include <cuda_runtime.h>
#include <cuda_bf16.h>
#include <cstdint>

#define N_MAX 100352
#define E_MAX 1000000
#define HID 64

// ---------------- device scratch ----------------
__device__ float g_H [100000 * HID];
__device__ float g_HW[100000 * HID];
__device__ float g_dinv[N_MAX];
__device__ int   g_hist[N_MAX];
__device__ int   g_offs[N_MAX];
__device__ int   g_cur [N_MAX];
__device__ int   g_part[256];
__device__ int   g_esrc[E_MAX];
__device__ int   g_is64;

// ---------------- edge access ----------------
__device__ __forceinline__ int edge_at(const void* ei, int idx) {
    if (g_is64) return (int)((const long long*)ei)[idx];
    return ((const int*)ei)[idx];
}

// ---------------- zero hist + dtype detect (merged) ----------------
__global__ void k_zero_detect(const unsigned long long* __restrict__ ei, int n) {
    int i = blockIdx.x * blockDim.x + threadIdx.x;
    if (i < n) g_hist[i] = 0;
    if (blockIdx.x == 0) {
        int local = 0;
        for (int j = threadIdx.x; j < 1024; j += blockDim.x)
            if ((ei[j] >> 32) != 0ull) local = 1;
        int any = __syncthreads_or(local);
        if (threadIdx.x == 0) g_is64 = (any == 0);
    }
}

__global__ void k_hist(const void* __restrict__ ei, int E) {
    int e = blockIdx.x * blockDim.x + threadIdx.x;
    if (e < E) atomicAdd(&g_hist[edge_at(ei, E + e)], 1);
}

// ---------------- scan1 (+dinv merged) ----------------
__global__ void k_scan1(int n) {
    int idx = blockIdx.x * 512 + threadIdx.x;
    int v = (idx < n) ? g_hist[idx] : 0;
    if (idx < n) g_dinv[idx] = rsqrtf((float)v + 1.0f);   // +1 self loop
    int lane = threadIdx.x & 31, wid = threadIdx.x >> 5;
    int inc = v;
    #pragma unroll
    for (int o = 1; o < 32; o <<= 1) {
        int t = __shfl_up_sync(0xffffffffu, inc, o);
        if (lane >= o) inc += t;
    }
    __shared__ int wsum[16];
    if (lane == 31) wsum[wid] = inc;
    __syncthreads();
    if (wid == 0) {
        int s = (lane < 16) ? wsum[lane] : 0;
        #pragma unroll
        for (int o = 1; o < 16; o <<= 1) {
            int t = __shfl_up_sync(0xffffffffu, s, o);
            if (lane >= o) s += t;
        }
        if (lane < 16) wsum[lane] = s;
    }
    __syncthreads();
    int base = (wid > 0) ? wsum[wid - 1] : 0;
    if (idx < n) g_offs[idx] = base + inc - v;
    if (threadIdx.x == 0) g_part[blockIdx.x] = wsum[15];
}

__global__ void k_scan2(int nb) {
    int t = threadIdx.x;
    int v = (t < nb) ? g_part[t] : 0;
    int lane = t & 31, wid = t >> 5;
    int inc = v;
    #pragma unroll
    for (int o = 1; o < 32; o <<= 1) {
        int s = __shfl_up_sync(0xffffffffu, inc, o);
        if (lane >= o) inc += s;
    }
    __shared__ int wsum[8];
    if (lane == 31) wsum[wid] = inc;
    __syncthreads();
    if (wid == 0) {
        int s = (lane < 8) ? wsum[lane] : 0;
        #pragma unroll
        for (int o = 1; o < 8; o <<= 1) {
            int u = __shfl_up_sync(0xffffffffu, s, o);
            if (lane >= o) s += u;
        }
        if (lane < 8) wsum[lane] = s;
    }
    __syncthreads();
    int base = (wid > 0) ? wsum[wid - 1] : 0;
    if (t < nb) g_part[t] = base + inc - v;
}

__global__ void k_scan3(int n) {
    int idx = blockIdx.x * 512 + threadIdx.x;
    if (idx < n) {
        int o = g_offs[idx] + g_part[blockIdx.x];
        g_offs[idx] = o;
        g_cur[idx]  = o;
    }
}

__global__ void k_place(const void* __restrict__ ei, int E) {
    int e = blockIdx.x * blockDim.x + threadIdx.x;
    if (e < E) {
        int s = edge_at(ei, e);
        int d = edge_at(ei, E + e);
        int pos = atomicAdd(&g_cur[d], 1);
        g_esrc[pos] = s;
    }
}

// ---------------- GEMM: C[n,64] = A[n,K] @ W[K,64] (+bias) ----------------
// 64x64 tile / block, 256 threads (16x16), 4x4 per thread — R3 proven config.
__global__ __launch_bounds__(256) void k_gemm(
    const float* __restrict__ Aext, const float* __restrict__ W,
    const float* __restrict__ bias, int dst_hw, int n, int K)
{
    const float* A = Aext ? Aext : (const float*)g_H;
    float* C = dst_hw ? g_HW : g_H;

    __shared__ float As[64][64];
    __shared__ float Ws[64][64];
    int row0 = blockIdx.x * 64;
    int tid = threadIdx.x;
    int tr = tid >> 4, tc = tid & 15;
    float acc[4][4];
    #pragma unroll
    for (int r = 0; r < 4; r++)
        #pragma unroll
        for (int c = 0; c < 4; c++) acc[r][c] = 0.0f;

    for (int k0 = 0; k0 < K; k0 += 64) {
        #pragma unroll
        for (int i = tid; i < 64 * 16; i += 256) {
            int r = i >> 4, c4 = (i & 15) << 2;
            int gr = row0 + r;
            float4 v = (gr < n) ? *(const float4*)(A + (size_t)gr * K + k0 + c4)
                                : make_float4(0.f, 0.f, 0.f, 0.f);
            *(float4*)&As[r][c4] = v;
        }
        #pragma unroll
        for (int i = tid; i < 64 * 16; i += 256) {
            int r = i >> 4, c4 = (i & 15) << 2;
            *(float4*)&Ws[r][c4] = *(const float4*)(W + (size_t)(k0 + r) * 64 + c4);
        }
        __syncthreads();
        #pragma unroll
        for (int kk = 0; kk < 64; kk += 4) {
            float4 a[4], b[4];
            #pragma unroll
            for (int r = 0; r < 4; r++) a[r] = *(float4*)&As[tr * 4 + r][kk];
            #pragma unroll
            for (int j = 0; j < 4; j++) b[j] = *(float4*)&Ws[kk + j][tc * 4];
            #pragma unroll
            for (int j = 0; j < 4; j++) {
                #pragma unroll
                for (int r = 0; r < 4; r++) {
                    float av = (j == 0) ? a[r].x : (j == 1) ? a[r].y
                             : (j == 2) ? a[r].z : a[r].w;
                    acc[r][0] = fmaf(av, b[j].x, acc[r][0]);
                    acc[r][1] = fmaf(av, b[j].y, acc[r][1]);
                    acc[r][2] = fmaf(av, b[j].z, acc[r][2]);
                    acc[r][3] = fmaf(av, b[j].w, acc[r][3]);
                }
            }
        }
        __syncthreads();
    }
    float4 bb = bias ? *(const float4*)(bias + tc * 4) : make_float4(0.f, 0.f, 0.f, 0.f);
    #pragma unroll
    for (int r = 0; r < 4; r++) {
        int gr = row0 + tr * 4 + r;
        if (gr < n) {
            float4 o = make_float4(acc[r][0] + bb.x, acc[r][1] + bb.y,
                                   acc[r][2] + bb.z, acc[r][3] + bb.w);
            *(float4*)(C + (size_t)gr * 64 + tc * 4) = o;
        }
    }
}

// ---------------- fused aggregate + bias + LN (+ReLU+residual) ----------
__global__ void k_agg(const float* __restrict__ bias, const float* __restrict__ gma,
                      const float* __restrict__ beta, float* __restrict__ out_ext,
                      int n, int relu_res)
{
    int node = (blockIdx.x * blockDim.x + threadIdx.x) >> 5;
    if (node >= n) return;
    int lane = threadIdx.x & 31;
    float* out = out_ext ? out_ext : (float*)g_H;

    float di = g_dinv[node];
    float2 acc = ((const float2*)(g_HW + (size_t)node * HID))[lane];
    float self = di * di;
    acc.x *= self; acc.y *= self;
    float2 accB = make_float2(0.f, 0.f);

    int e = g_offs[node];
    int e_end = e + g_hist[node];
    for (; e + 2 <= e_end; e += 2) {
        int sa = g_esrc[e];
        int sb = g_esrc[e + 1];
        float na = g_dinv[sa] * di;
        float nb = g_dinv[sb] * di;
        float2 va = ((const float2*)(g_HW + (size_t)sa * HID))[lane];
        float2 vb = ((const float2*)(g_HW + (size_t)sb * HID))[lane];
        acc.x  = fmaf(va.x, na, acc.x);  acc.y  = fmaf(va.y, na, acc.y);
        accB.x = fmaf(vb.x, nb, accB.x); accB.y = fmaf(vb.y, nb, accB.y);
    }
    if (e < e_end) {
        int sa = g_esrc[e];
        float na = g_dinv[sa] * di;
        float2 va = ((const float2*)(g_HW + (size_t)sa * HID))[lane];
        acc.x = fmaf(va.x, na, acc.x); acc.y = fmaf(va.y, na, acc.y);
    }
    acc.x += accB.x; acc.y += accB.y;

    float2 bb = ((const float2*)bias)[lane];
    acc.x += bb.x; acc.y += bb.y;

    float sum = acc.x + acc.y;
    #pragma unroll
    for (int o = 16; o; o >>= 1) sum += __shfl_xor_sync(0xffffffffu, sum, o);
    float mu = sum * (1.0f / 64.0f);
    float dx = acc.x - mu, dy = acc.y - mu;
    float vs = dx * dx + dy * dy;
    #pragma unroll
    for (int o = 16; o; o >>= 1) vs += __shfl_xor_sync(0xffffffffu, vs, o);
    float rstd = rsqrtf(vs * (1.0f / 64.0f) + 1e-5f);
    float2 gg = ((const float2*)gma)[lane];
    float2 be = ((const float2*)beta)[lane];
    float ox = dx * rstd * gg.x + be.x;
    float oy = dy * rstd * gg.y + be.y;

    if (relu_res) {
        float2 r = ((const float2*)(g_H + (size_t)node * HID))[lane];
        ox = fmaxf(ox, 0.0f) + r.x;
        oy = fmaxf(oy, 0.0f) + r.y;
    }
    ((float2*)(out + (size_t)node * HID))[lane] = make_float2(ox, oy);
}

// ---------------- launch ----------------
extern "C" void kernel_launch(void* const* d_in, const int* in_sizes, int n_in,
                              void* d_out, int out_size)
{
    const float* x      = (const float*)d_in[0];
    const void*  ei     = d_in[1];
    const float* proj_w = (const float*)d_in[2];
    const float* proj_b = (const float*)d_in[3];
    const float* w[3]  = { (const float*)d_in[4],  (const float*)d_in[8],  (const float*)d_in[12] };
    const float* b[3]  = { (const float*)d_in[5],  (const float*)d_in[9],  (const float*)d_in[13] };
    const float* gm[3] = { (const float*)d_in[6],  (const float*)d_in[10], (const float*)d_in[14] };
    const float* bt[3] = { (const float*)d_in[7],  (const float*)d_in[11], (const float*)d_in[15] };

    int n = in_sizes[0] / 128;    // 100000
    int E = in_sizes[1] / 2;      // 1000000
    float* out = (float*)d_out;

    int nb512 = (n + 511) / 512;

    k_zero_detect<<<(n + 255) / 256, 256>>>((const unsigned long long*)ei, n);
    k_hist<<<(E + 255) / 256, 256>>>(ei, E);
    k_scan1<<<nb512, 512>>>(n);
    k_scan2<<<1, 256>>>(nb512);
    k_scan3<<<nb512, 512>>>(n);
    k_gemm<<<(n + 63) / 64, 256>>>(x, proj_w, proj_b, /*dst_hw=*/0, n, 128);
    k_place<<<(E + 255) / 256, 256>>>(ei, E);

    int agg_blocks = (n + 7) / 8;
    for (int l = 0; l < 3; l++) {
        k_gemm<<<(n + 63) / 64, 256>>>(nullptr, w[l], nullptr, /*dst_hw=*/1, n, 64);
        float* dst = (l < 2) ? nullptr : out;
        k_agg<<<agg_blocks, 256>>>(b[l], gm[l], bt[l], dst, n, (l < 2) ? 1 : 0);
    }
}

// round 6
// speedup vs baseline: 1.4566x; 1.0802x over previous
#include <cuda_runtime.h>
#include <cuda_bf16.h>
#include <cstdint>

#define N_MAX 100352
#define E_MAX 1000000
#define HID 64

// ---------------- device scratch ----------------
__device__ float g_H [100000 * HID];
__device__ float g_HW[100000 * HID];
__device__ float g_dinv[N_MAX];
__device__ int   g_hist[N_MAX];
__device__ int   g_offs[N_MAX];
__device__ int   g_cur [N_MAX];
__device__ int   g_part[256];
__device__ int   g_esrc[E_MAX];
__device__ int   g_is64;

// ---------------- edge access ----------------
__device__ __forceinline__ int edge_at(const void* ei, int idx) {
    if (g_is64) return (int)((const long long*)ei)[idx];
    return ((const int*)ei)[idx];
}

// ---------------- zero hist + dtype detect (merged) ----------------
__global__ void k_zero_detect(const unsigned long long* __restrict__ ei, int n) {
    int i = blockIdx.x * blockDim.x + threadIdx.x;
    if (i < n) g_hist[i] = 0;
    if (blockIdx.x == 0) {
        int local = 0;
        for (int j = threadIdx.x; j < 1024; j += blockDim.x)
            if ((ei[j] >> 32) != 0ull) local = 1;
        int any = __syncthreads_or(local);
        if (threadIdx.x == 0) g_is64 = (any == 0);
    }
}

__global__ void k_hist(const void* __restrict__ ei, int E) {
    int e = blockIdx.x * blockDim.x + threadIdx.x;
    if (e < E) atomicAdd(&g_hist[edge_at(ei, E + e)], 1);
}

// ---------------- scan1 (+dinv merged) ----------------
__global__ void k_scan1(int n) {
    int idx = blockIdx.x * 512 + threadIdx.x;
    int v = (idx < n) ? g_hist[idx] : 0;
    if (idx < n) g_dinv[idx] = rsqrtf((float)v + 1.0f);
    int lane = threadIdx.x & 31, wid = threadIdx.x >> 5;
    int inc = v;
    #pragma unroll
    for (int o = 1; o < 32; o <<= 1) {
        int t = __shfl_up_sync(0xffffffffu, inc, o);
        if (lane >= o) inc += t;
    }
    __shared__ int wsum[16];
    if (lane == 31) wsum[wid] = inc;
    __syncthreads();
    if (wid == 0) {
        int s = (lane < 16) ? wsum[lane] : 0;
        #pragma unroll
        for (int o = 1; o < 16; o <<= 1) {
            int t = __shfl_up_sync(0xffffffffu, s, o);
            if (lane >= o) s += t;
        }
        if (lane < 16) wsum[lane] = s;
    }
    __syncthreads();
    int base = (wid > 0) ? wsum[wid - 1] : 0;
    if (idx < n) g_offs[idx] = base + inc - v;
    if (threadIdx.x == 0) g_part[blockIdx.x] = wsum[15];
}

__global__ void k_scan2(int nb) {
    int t = threadIdx.x;
    int v = (t < nb) ? g_part[t] : 0;
    int lane = t & 31, wid = t >> 5;
    int inc = v;
    #pragma unroll
    for (int o = 1; o < 32; o <<= 1) {
        int s = __shfl_up_sync(0xffffffffu, inc, o);
        if (lane >= o) inc += s;
    }
    __shared__ int wsum[8];
    if (lane == 31) wsum[wid] = inc;
    __syncthreads();
    if (wid == 0) {
        int s = (lane < 8) ? wsum[lane] : 0;
        #pragma unroll
        for (int o = 1; o < 8; o <<= 1) {
            int u = __shfl_up_sync(0xffffffffu, s, o);
            if (lane >= o) s += u;
        }
        if (lane < 8) wsum[lane] = s;
    }
    __syncthreads();
    int base = (wid > 0) ? wsum[wid - 1] : 0;
    if (t < nb) g_part[t] = base + inc - v;
}

__global__ void k_scan3(int n) {
    int idx = blockIdx.x * 512 + threadIdx.x;
    if (idx < n) {
        int o = g_offs[idx] + g_part[blockIdx.x];
        g_offs[idx] = o;
        g_cur[idx]  = o;
    }
}

__global__ void k_place(const void* __restrict__ ei, int E) {
    int e = blockIdx.x * blockDim.x + threadIdx.x;
    if (e < E) {
        int s = edge_at(ei, e);
        int d = edge_at(ei, E + e);
        int pos = atomicAdd(&g_cur[d], 1);
        g_esrc[pos] = s;
    }
}

// ---------------- bf16 split helpers ----------------
__device__ __forceinline__ unsigned short bits_of(__nv_bfloat16 h) {
    return *(unsigned short*)&h;
}
// split float -> (hi, lo) bf16; pack two k-adjacent values into one b32
__device__ __forceinline__ void split2(float x, float y, unsigned& hi, unsigned& lo) {
    __nv_bfloat16 hx = __float2bfloat16_rn(x);
    __nv_bfloat16 hy = __float2bfloat16_rn(y);
    __nv_bfloat16 lx = __float2bfloat16_rn(x - __bfloat162float(hx));
    __nv_bfloat16 ly = __float2bfloat16_rn(y - __bfloat162float(hy));
    hi = (unsigned)bits_of(hx) | ((unsigned)bits_of(hy) << 16);
    lo = (unsigned)bits_of(lx) | ((unsigned)bits_of(ly) << 16);
}

__device__ __forceinline__ void mma16816(float* c, const unsigned* a,
                                         unsigned b0, unsigned b1) {
    asm volatile(
        "mma.sync.aligned.m16n8k16.row.col.f32.bf16.bf16.f32 "
        "{%0,%1,%2,%3}, {%4,%5,%6,%7}, {%8,%9}, {%0,%1,%2,%3};"
        : "+f"(c[0]), "+f"(c[1]), "+f"(c[2]), "+f"(c[3])
        : "r"(a[0]), "r"(a[1]), "r"(a[2]), "r"(a[3]), "r"(b0), "r"(b1));
}

// ---------------- tensor GEMM: C[n,64] = A[n,K] @ W[K,64] (+bias) --------
// bf16x3 split for ~fp32 accuracy. 128 rows/block (8 warps x m16).
// A source: Aext if non-null else g_H. C dest: dst=0 -> g_H, 1 -> g_HW, 2 -> out_ext.
__global__ __launch_bounds__(256) void k_tgemm(
    const float* __restrict__ Aext, const float* __restrict__ W,
    const float* __restrict__ bias, float* __restrict__ out_ext,
    int dst, int n, int K)
{
    const float* A = Aext ? Aext : (const float*)g_H;
    float* C = (dst == 0) ? (float*)g_H : (dst == 1) ? (float*)g_HW : out_ext;

    // W transposed: [n][k], hi/lo bf16, stride 72 (bank-conflict-free frag reads)
    __shared__ __nv_bfloat16 Wh[64][72];
    __shared__ __nv_bfloat16 Wl[64][72];

    int tid = threadIdx.x;
    for (int base = 0; base < K * 64; base += 256 * 16) {
        #pragma unroll
        for (int u = 0; u < 16; u++) {
            int i = base + tid * 16 + u;          // contiguous 16 per thread
            if (i < K * 64) {
                int kk = i >> 6, nn = i & 63;
                float wv = W[i];
                __nv_bfloat16 h = __float2bfloat16_rn(wv);
                __nv_bfloat16 l = __float2bfloat16_rn(wv - __bfloat162float(h));
                // note: for K=128 we fold k into two halves handled below
                if (K == 64) { Wh[nn][kk] = h; Wl[nn][kk] = l; }
            }
        }
        if (K == 64) break;
        break;
    }
    // K=128 path: loop k-half (two 64-wide smem passes)
    int row_base = blockIdx.x * 128;
    int warp = tid >> 5, lane = tid & 31;
    int r = lane >> 2, q = lane & 3;
    int row0 = row_base + warp * 16 + r;
    int rowA0 = min(row0, n - 1);
    int rowA1 = min(row0 + 8, n - 1);

    float c[8][4];
    #pragma unroll
    for (int nf = 0; nf < 8; nf++)
        #pragma unroll
        for (int j = 0; j < 4; j++) c[nf][j] = 0.0f;

    int khalves = K >> 6;          // 1 or 2
    for (int kh = 0; kh < khalves; kh++) {
        if (K == 128) {
            // (re)fill smem with W rows [kh*64, kh*64+64)
            __syncthreads();
            for (int i = tid; i < 64 * 64; i += 256) {
                int kk = i >> 6, nn = i & 63;
                float wv = W[(kh * 64 + kk) * 64 + nn];
                __nv_bfloat16 h = __float2bfloat16_rn(wv);
                __nv_bfloat16 l = __float2bfloat16_rn(wv - __bfloat162float(h));
                Wh[nn][kk] = h; Wl[nn][kk] = l;
            }
        }
        __syncthreads();

        #pragma unroll
        for (int kc = 0; kc < 4; kc++) {
            int kbase = kh * 64 + kc * 16 + q * 2;
            const float* p0 = A + (size_t)rowA0 * K + kbase;
            const float* p1 = A + (size_t)rowA1 * K + kbase;
            float2 v0 = *(const float2*)p0;
            float2 v1 = *(const float2*)p1;
            float2 v2 = *(const float2*)(p0 + 8);
            float2 v3 = *(const float2*)(p1 + 8);
            unsigned ah[4], al[4];
            split2(v0.x, v0.y, ah[0], al[0]);
            split2(v1.x, v1.y, ah[1], al[1]);
            split2(v2.x, v2.y, ah[2], al[2]);
            split2(v3.x, v3.y, ah[3], al[3]);

            #pragma unroll
            for (int nf = 0; nf < 8; nf++) {
                int bn = nf * 8 + r;
                int bk = kc * 16 + q * 2;
                unsigned bh0 = *(const unsigned*)&Wh[bn][bk];
                unsigned bh1 = *(const unsigned*)&Wh[bn][bk + 8];
                unsigned bl0 = *(const unsigned*)&Wl[bn][bk];
                unsigned bl1 = *(const unsigned*)&Wl[bn][bk + 8];
                mma16816(c[nf], ah, bh0, bh1);
                mma16816(c[nf], al, bh0, bh1);
                mma16816(c[nf], ah, bl0, bl1);
            }
        }
    }

    // epilogue
    #pragma unroll
    for (int nf = 0; nf < 8; nf++) {
        int col = nf * 8 + q * 2;
        float bx = 0.f, by = 0.f;
        if (bias) { float2 bb = *(const float2*)(bias + col); bx = bb.x; by = bb.y; }
        if (row0 < n)
            *(float2*)(C + (size_t)row0 * 64 + col) =
                make_float2(c[nf][0] + bx, c[nf][1] + by);
        if (row0 + 8 < n)
            *(float2*)(C + (size_t)(row0 + 8) * 64 + col) =
                make_float2(c[nf][2] + bx, c[nf][3] + by);
    }
}

// ---------------- fused aggregate + bias + LN (+ReLU+residual) ----------
__global__ void k_agg(const float* __restrict__ bias, const float* __restrict__ gma,
                      const float* __restrict__ beta, float* __restrict__ out_ext,
                      int n, int relu_res)
{
    int node = (blockIdx.x * blockDim.x + threadIdx.x) >> 5;
    if (node >= n) return;
    int lane = threadIdx.x & 31;
    float* out = out_ext ? out_ext : (float*)g_H;

    float di = g_dinv[node];
    float2 acc = ((const float2*)(g_HW + (size_t)node * HID))[lane];
    float self = di * di;
    acc.x *= self; acc.y *= self;
    float2 accB = make_float2(0.f, 0.f);

    int e = g_offs[node];
    int e_end = e + g_hist[node];
    for (; e + 2 <= e_end; e += 2) {
        int sa = g_esrc[e];
        int sb = g_esrc[e + 1];
        float na = g_dinv[sa] * di;
        float nb = g_dinv[sb] * di;
        float2 va = ((const float2*)(g_HW + (size_t)sa * HID))[lane];
        float2 vb = ((const float2*)(g_HW + (size_t)sb * HID))[lane];
        acc.x  = fmaf(va.x, na, acc.x);  acc.y  = fmaf(va.y, na, acc.y);
        accB.x = fmaf(vb.x, nb, accB.x); accB.y = fmaf(vb.y, nb, accB.y);
    }
    if (e < e_end) {
        int sa = g_esrc[e];
        float na = g_dinv[sa] * di;
        float2 va = ((const float2*)(g_HW + (size_t)sa * HID))[lane];
        acc.x = fmaf(va.x, na, acc.x); acc.y = fmaf(va.y, na, acc.y);
    }
    acc.x += accB.x; acc.y += accB.y;

    float2 bb = ((const float2*)bias)[lane];
    acc.x += bb.x; acc.y += bb.y;

    float sum = acc.x + acc.y;
    #pragma unroll
    for (int o = 16; o; o >>= 1) sum += __shfl_xor_sync(0xffffffffu, sum, o);
    float mu = sum * (1.0f / 64.0f);
    float dx = acc.x - mu, dy = acc.y - mu;
    float vs = dx * dx + dy * dy;
    #pragma unroll
    for (int o = 16; o; o >>= 1) vs += __shfl_xor_sync(0xffffffffu, vs, o);
    float rstd = rsqrtf(vs * (1.0f / 64.0f) + 1e-5f);
    float2 gg = ((const float2*)gma)[lane];
    float2 be = ((const float2*)beta)[lane];
    float ox = dx * rstd * gg.x + be.x;
    float oy = dy * rstd * gg.y + be.y;

    if (relu_res) {
        float2 r = ((const float2*)(g_H + (size_t)node * HID))[lane];
        ox = fmaxf(ox, 0.0f) + r.x;
        oy = fmaxf(oy, 0.0f) + r.y;
    }
    ((float2*)(out + (size_t)node * HID))[lane] = make_float2(ox, oy);
}

// ---------------- launch ----------------
extern "C" void kernel_launch(void* const* d_in, const int* in_sizes, int n_in,
                              void* d_out, int out_size)
{
    const float* x      = (const float*)d_in[0];
    const void*  ei     = d_in[1];
    const float* proj_w = (const float*)d_in[2];
    const float* proj_b = (const float*)d_in[3];
    const float* w[3]  = { (const float*)d_in[4],  (const float*)d_in[8],  (const float*)d_in[12] };
    const float* b[3]  = { (const float*)d_in[5],  (const float*)d_in[9],  (const float*)d_in[13] };
    const float* gm[3] = { (const float*)d_in[6],  (const float*)d_in[10], (const float*)d_in[14] };
    const float* bt[3] = { (const float*)d_in[7],  (const float*)d_in[11], (const float*)d_in[15] };

    int n = in_sizes[0] / 128;    // 100000
    int E = in_sizes[1] / 2;      // 1000000
    float* out = (float*)d_out;

    int nb512 = (n + 511) / 512;
    int gemm_blocks = (n + 127) / 128;

    k_zero_detect<<<(n + 255) / 256, 256>>>((const unsigned long long*)ei, n);   // 0
    k_hist<<<(E + 255) / 256, 256>>>(ei, E);                                      // 1
    k_scan1<<<nb512, 512>>>(n);                                                   // 2
    k_scan2<<<1, 256>>>(nb512);                                                   // 3
    k_scan3<<<nb512, 512>>>(n);                                                   // 4
    k_tgemm<<<gemm_blocks, 256>>>(x, proj_w, proj_b, nullptr, /*dst=*/0, n, 128); // 5 (proj)
    k_place<<<(E + 255) / 256, 256>>>(ei, E);                                     // 6

    int agg_blocks = (n + 7) / 8;
    for (int l = 0; l < 3; l++) {
        k_tgemm<<<gemm_blocks, 256>>>(nullptr, w[l], nullptr, nullptr, /*dst=*/1, n, 64);
        float* dst = (l < 2) ? nullptr : out;
        k_agg<<<agg_blocks, 256>>>(b[l], gm[l], bt[l], dst, n, (l < 2) ? 1 : 0);
    }
}